// round 4
// baseline (speedup 1.0000x reference)
#include <cuda_runtime.h>
#include <cstdint>

#define Hc 224
#define Wc 224
#define Cc 96
#define CPc 48          // channel pairs (float2 as ull)
#define TAPS 49
#define WT 8            // per-thread output width (float2 cols)

typedef unsigned long long ull;

// Flipped kernel, transposed to [tap][cp] packed float2
__device__ ull g_wT[TAPS * CPc];

__global__ void prep_kernel(const float* __restrict__ k) {
    int idx = blockIdx.x * blockDim.x + threadIdx.x;
    if (idx < TAPS * Cc) {
        int tap = idx / Cc, c = idx % Cc;
        int i = tap / 7, j = tap % 7;
        reinterpret_cast<float*>(g_wT)[tap * Cc + c] = k[c * TAPS + (6 - i) * 7 + (6 - j)];
    }
}

__device__ __forceinline__ void ffma2(ull& d, ull a, ull b) {
    asm("fma.rn.f32x2 %0, %1, %2, %0;" : "+l"(d) : "l"(a), "l"(b));
}

// Load one input row (14 float2) for this thread's column window.
template <bool FAST>
__device__ __forceinline__ void load_row(ull (&rb)[WT + 6],
                                         const ull* __restrict__ base,
                                         const ull* __restrict__ pfast,
                                         int cp, int w0, int h0, int ih) {
    if (FAST) {
        #pragma unroll
        for (int j = 0; j < WT + 6; j++)
            rb[j] = __ldg(pfast + ih * (Wc * CPc) + j * CPc);
    } else {
        int r = h0 - 3 + ih;
        if (r < 0) r += Hc;
        else if (r >= Hc) r -= Hc;
        const ull* rowp = base + (size_t)r * (Wc * CPc) + cp;
        #pragma unroll
        for (int j = 0; j < WT + 6; j++) {
            int wv = w0 - 3 + j;
            if (wv < 0) wv += Wc;
            else if (wv >= Wc) wv -= Wc;
            rb[j] = __ldg(rowp + wv * CPc);
        }
    }
}

// Thread tile: 2(h) x 8(w) float2 outputs for one channel pair.
// Row buffer double-buffered: row ih+1's LDGs are issued before row ih is
// consumed, hiding L2/DRAM latency inside the warp. Weight rows register-
// double-buffered: each of the 7 weight rows is LDS'd exactly once per tile.
template <bool FAST>
__device__ __forceinline__ void conv_tile(const ull* __restrict__ base,
                                          ull* __restrict__ obase,
                                          const ull* wsh,
                                          int cp, int w0, int h0) {
    ull acc0[WT], acc1[WT];
    #pragma unroll
    for (int i = 0; i < WT; i++) { acc0[i] = 0ull; acc1[i] = 0ull; }

    ull wbuf[2][7];
    ull rb[2][WT + 6];
    const ull* pfast = base + (ptrdiff_t)(h0 - 3) * (Wc * CPc) + (w0 - 3) * CPc + cp;

    load_row<FAST>(rb[0], base, pfast, cp, w0, h0, 0);

    #pragma unroll
    for (int ih = 0; ih < 8; ih++) {
        // Prefetch next row before consuming the current one
        if (ih < 7)
            load_row<FAST>(rb[(ih + 1) & 1], base, pfast, cp, w0, h0, ih + 1);

        const ull (&cur)[WT + 6] = rb[ih & 1];

        if (ih <= 6) {
            #pragma unroll
            for (int dw = 0; dw < 7; dw++)
                wbuf[ih & 1][dw] = wsh[(ih * 7 + dw) * CPc + cp];
            #pragma unroll
            for (int dw = 0; dw < 7; dw++) {
                ull wv = wbuf[ih & 1][dw];
                #pragma unroll
                for (int ow = 0; ow < WT; ow++) ffma2(acc0[ow], wv, cur[ow + dw]);
            }
        }
        if (ih >= 1) {
            #pragma unroll
            for (int dw = 0; dw < 7; dw++) {
                ull wv = wbuf[(ih & 1) ^ 1][dw];
                #pragma unroll
                for (int ow = 0; ow < WT; ow++) ffma2(acc1[ow], wv, cur[ow + dw]);
            }
        }
    }

    ull* o0 = obase + (size_t)h0 * (Wc * CPc) + w0 * CPc + cp;
    ull* o1 = o0 + (Wc * CPc);
    #pragma unroll
    for (int ow = 0; ow < WT; ow++) {
        o0[ow * CPc] = acc0[ow];
        o1[ow * CPc] = acc1[ow];
    }
}

__global__ __launch_bounds__(192, 2) void conv_kernel(const float* __restrict__ xf,
                                                      float* __restrict__ outf) {
    __shared__ ull wsh[TAPS * CPc];
    const int tid = threadIdx.x;
    #pragma unroll
    for (int i = tid; i < TAPS * CPc; i += 192) wsh[i] = g_wT[i];
    __syncthreads();

    const int cp    = tid % 48;
    const int ty    = tid / 48;
    const int slice = blockIdx.z;
    const int w0    = blockIdx.x * WT;
    const int h0    = blockIdx.y * 8 + ty * 2;

    const ull* base = reinterpret_cast<const ull*>(xf) + (size_t)slice * (Hc * Wc * CPc);
    ull* obase      = reinterpret_cast<ull*>(outf)     + (size_t)slice * (Hc * Wc * CPc);

    const bool fast = (blockIdx.x >= 1) & (blockIdx.x <= (Wc / WT) - 2) &
                      (blockIdx.y >= 1) & (blockIdx.y <= 26);
    if (fast) conv_tile<true>(base, obase, wsh, cp, w0, h0);
    else      conv_tile<false>(base, obase, wsh, cp, w0, h0);
}

extern "C" void kernel_launch(void* const* d_in, const int* in_sizes, int n_in,
                              void* d_out, int out_size) {
    const float* x = (const float*)d_in[0];   // (2,8,224,224,96) fp32
    const float* k = (const float*)d_in[1];   // (96,1,7,7) fp32
    float* out = (float*)d_out;

    prep_kernel<<<(TAPS * Cc + 255) / 256, 256>>>(k);

    dim3 block(192);
    dim3 grid(Wc / WT, Hc / 8, 16);
    conv_kernel<<<grid, block>>>(x, out);
}

// round 5
// speedup vs baseline: 1.1121x; 1.1121x over previous
#include <cuda_runtime.h>
#include <cstdint>

#define Hc 224
#define Wc 224
#define Cc 96
#define CPc 48          // channel pairs (float2 as ull)
#define TAPS 49
#define WT 8            // per-thread output width (float2 cols)

typedef unsigned long long ull;

// Flipped kernel, transposed to [tap][cp] packed float2
__device__ ull g_wT[TAPS * CPc];

__global__ void prep_kernel(const float* __restrict__ k) {
    int idx = blockIdx.x * blockDim.x + threadIdx.x;
    if (idx < TAPS * Cc) {
        int tap = idx / Cc, c = idx % Cc;
        int i = tap / 7, j = tap % 7;
        reinterpret_cast<float*>(g_wT)[tap * Cc + c] = k[c * TAPS + (6 - i) * 7 + (6 - j)];
    }
}

__device__ __forceinline__ void ffma2(ull& d, ull a, ull b) {
    asm("fma.rn.f32x2 %0, %1, %2, %0;" : "+l"(d) : "l"(a), "l"(b));
}

// ---------------- FAST interior tile ----------------
// 2(h) x 8(w) float2 outputs. Loop over weight row dh; one single-buffered
// weight row (7 regs) serves both output rows: acc0 uses input row dh,
// acc1 uses input row dh+1. Input rows roll through a 2-row buffer; the
// row-(dh+2) LDG batch is issued between acc0's and acc1's FMA blocks.
__device__ __forceinline__ void conv_fast(const ull* __restrict__ base,
                                          ull* __restrict__ obase,
                                          const ull* wsh,
                                          int cp, int w0, int h0) {
    ull acc0[WT], acc1[WT];
    #pragma unroll
    for (int i = 0; i < WT; i++) { acc0[i] = 0ull; acc1[i] = 0ull; }

    const ull* p = base + (ptrdiff_t)(h0 - 3) * (Wc * CPc) + (w0 - 3) * CPc + cp;

    ull rb[2][WT + 6];
    #pragma unroll
    for (int j = 0; j < WT + 6; j++) rb[0][j] = __ldg(p + j * CPc);
    #pragma unroll
    for (int j = 0; j < WT + 6; j++) rb[1][j] = __ldg(p + (Wc * CPc) + j * CPc);

    #pragma unroll
    for (int dh = 0; dh < 7; dh++) {
        ull w[7];
        #pragma unroll
        for (int dw = 0; dw < 7; dw++) w[dw] = wsh[(dh * 7 + dw) * CPc + cp];

        // output row h0: input row index dh (buffer dh&1), last use of that row
        #pragma unroll
        for (int dw = 0; dw < 7; dw++)
            #pragma unroll
            for (int ow = 0; ow < WT; ow++)
                ffma2(acc0[ow], w[dw], rb[dh & 1][ow + dw]);

        // prefetch input row dh+2 into the buffer just freed by acc0
        if (dh < 6) {
            #pragma unroll
            for (int j = 0; j < WT + 6; j++)
                rb[dh & 1][j] = __ldg(p + (dh + 2) * (Wc * CPc) + j * CPc);
        }

        // output row h0+1: input row index dh+1 (buffer (dh+1)&1)
        #pragma unroll
        for (int dw = 0; dw < 7; dw++)
            #pragma unroll
            for (int ow = 0; ow < WT; ow++)
                ffma2(acc1[ow], w[dw], rb[(dh + 1) & 1][ow + dw]);
    }

    ull* o0 = obase + (size_t)h0 * (Wc * CPc) + w0 * CPc + cp;
    ull* o1 = o0 + (Wc * CPc);
    #pragma unroll
    for (int ow = 0; ow < WT; ow++) {
        o0[ow * CPc] = acc0[ow];
        o1[ow * CPc] = acc1[ow];
    }
}

// ---------------- SLOW boundary tile (R2 logic, wrap handling) ----------------
__device__ __forceinline__ void conv_slow(const ull* __restrict__ base,
                                          ull* __restrict__ obase,
                                          const ull* wsh,
                                          int cp, int w0, int h0) {
    ull acc0[WT], acc1[WT];
    #pragma unroll
    for (int i = 0; i < WT; i++) { acc0[i] = 0ull; acc1[i] = 0ull; }

    int woff[WT + 6];
    #pragma unroll
    for (int j = 0; j < WT + 6; j++) {
        int wv = w0 - 3 + j;
        if (wv < 0) wv += Wc;
        else if (wv >= Wc) wv -= Wc;
        woff[j] = wv * CPc + cp;
    }

    #pragma unroll
    for (int ih = 0; ih < 8; ih++) {
        int r = h0 - 3 + ih;
        if (r < 0) r += Hc;
        else if (r >= Hc) r -= Hc;
        const ull* rowp = base + (size_t)r * (Wc * CPc);
        ull rb[WT + 6];
        #pragma unroll
        for (int j = 0; j < WT + 6; j++) rb[j] = __ldg(rowp + woff[j]);

        if (ih <= 6) {
            #pragma unroll
            for (int dw = 0; dw < 7; dw++) {
                ull wv = wsh[(ih * 7 + dw) * CPc + cp];
                #pragma unroll
                for (int ow = 0; ow < WT; ow++) ffma2(acc0[ow], wv, rb[ow + dw]);
            }
        }
        if (ih >= 1) {
            #pragma unroll
            for (int dw = 0; dw < 7; dw++) {
                ull wv = wsh[((ih - 1) * 7 + dw) * CPc + cp];
                #pragma unroll
                for (int ow = 0; ow < WT; ow++) ffma2(acc1[ow], wv, rb[ow + dw]);
            }
        }
    }

    ull* o0 = obase + (size_t)h0 * (Wc * CPc) + w0 * CPc + cp;
    ull* o1 = o0 + (Wc * CPc);
    #pragma unroll
    for (int ow = 0; ow < WT; ow++) {
        o0[ow * CPc] = acc0[ow];
        o1[ow * CPc] = acc1[ow];
    }
}

__global__ __launch_bounds__(192, 3) void conv_kernel(const float* __restrict__ xf,
                                                      float* __restrict__ outf) {
    __shared__ ull wsh[TAPS * CPc];
    const int tid = threadIdx.x;
    #pragma unroll
    for (int i = tid; i < TAPS * CPc; i += 192) wsh[i] = g_wT[i];
    __syncthreads();

    const int cp    = tid % 48;
    const int ty    = tid / 48;
    const int slice = blockIdx.z;
    const int w0    = blockIdx.x * WT;
    const int h0    = blockIdx.y * 8 + ty * 2;

    const ull* base = reinterpret_cast<const ull*>(xf) + (size_t)slice * (Hc * Wc * CPc);
    ull* obase      = reinterpret_cast<ull*>(outf)     + (size_t)slice * (Hc * Wc * CPc);

    const bool fast = (blockIdx.x >= 1) & (blockIdx.x <= (Wc / WT) - 2) &
                      (blockIdx.y >= 1) & (blockIdx.y <= 26);
    if (fast) conv_fast(base, obase, wsh, cp, w0, h0);
    else      conv_slow(base, obase, wsh, cp, w0, h0);
}

extern "C" void kernel_launch(void* const* d_in, const int* in_sizes, int n_in,
                              void* d_out, int out_size) {
    const float* x = (const float*)d_in[0];   // (2,8,224,224,96) fp32
    const float* k = (const float*)d_in[1];   // (96,1,7,7) fp32
    float* out = (float*)d_out;

    prep_kernel<<<(TAPS * Cc + 255) / 256, 256>>>(k);

    dim3 block(192);
    dim3 grid(Wc / WT, Hc / 8, 16);
    conv_kernel<<<grid, block>>>(x, out);
}